// round 2
// baseline (speedup 1.0000x reference)
#include <cuda_runtime.h>
#include <math.h>

#define N_NODES 8192
#define MAXD 128

constexpr int BR = 32;   // rows per GEMM block
constexpr int KC = 32;   // k-chunk
constexpr int GB = N_NODES / BR;   // 256 GEMM blocks
constexpr int SCANB = 256;         // scan side-blocks per fused kernel

// ---------------- scratch (device globals; no allocation allowed) ----------
__device__ __align__(16) float d_h1 [N_NODES * 64];
__device__ __align__(16) float d_h  [N_NODES * 128];
__device__ __align__(16) float d_msg[N_NODES * 128];
__device__ __align__(16) float d_g  [N_NODES * 128];
__device__ __align__(16) float d_f  [N_NODES * 256];   // [g | h]
__device__ __align__(16) float d_p1 [N_NODES * 128];
__device__ __align__(16) float d_p2 [N_NODES * 64];
__device__ float d_dinv[N_NODES];
__device__ int   d_cnt [N_NODES];
__device__ int   d_nbr [N_NODES * MAXD];

// work-stealing state for the adjacency scan
__device__ int g_rowctr;
__device__ int g_fin[4];
__device__ int g_stop[4];

__global__ void init_kernel()
{
    g_rowctr = 0;
#pragma unroll
    for (int i = 0; i < 4; i++) { g_fin[i] = 0; g_stop[i] = 0; }
}

// ---------------- adjacency row scan (work-stealing) ------------------------
// Builds capped CSR + dinv. kid<3: stop early once kernel kid's GEMM blocks
// finish (hint only — every stolen row is always fully processed, so the
// final CSR/dinv contents are deterministic).
__device__ __forceinline__ void scan_rows(const float* __restrict__ adj, int kid)
{
    __shared__ int s_row;
    __shared__ int s_cnt;
    const int tid = threadIdx.x;

    for (;;) {
        if (tid == 0) {
            int stop = (kid < 3) ? *((volatile int*)&g_stop[kid]) : 0;
            s_row = stop ? N_NODES : atomicAdd(&g_rowctr, 1);
            s_cnt = 0;
        }
        __syncthreads();
        const int row = s_row;
        if (row >= N_NODES) return;

        const float4* a4 = (const float4*)(adj + (size_t)row * N_NODES);
        int* nbr = d_nbr + (size_t)row * MAXD;
        for (int i = tid; i < N_NODES / 4; i += 256) {
            float4 v = a4[i];
            if (v.x != 0.f) { int p = atomicAdd(&s_cnt, 1); if (p < MAXD) nbr[p] = i * 4 + 0; }
            if (v.y != 0.f) { int p = atomicAdd(&s_cnt, 1); if (p < MAXD) nbr[p] = i * 4 + 1; }
            if (v.z != 0.f) { int p = atomicAdd(&s_cnt, 1); if (p < MAXD) nbr[p] = i * 4 + 2; }
            if (v.w != 0.f) { int p = atomicAdd(&s_cnt, 1); if (p < MAXD) nbr[p] = i * 4 + 3; }
        }
        __syncthreads();
        if (tid == 0) {
            int cn = s_cnt;
            d_cnt[row]  = cn < MAXD ? cn : MAXD;
            d_dinv[row] = rsqrtf((float)cn + 1.0f);   // +1 self loop
        }
        __syncthreads();   // all atomics done before next iteration resets s_cnt
    }
}

__global__ void __launch_bounds__(256)
scan_finish_kernel(const float* __restrict__ adj)
{
    scan_rows(adj, 3);   // kid=3 -> never stops early; drains all rows
}

// ---------------- register-tiled GEMM body: out = act(in @ W^T + b) --------
// Weight tile stored transposed with a per-k group rotation so that both the
// scalar STS (transpose) and the float4 LDS are bank-conflict-free.
template <int K, int M, bool RELU>
__device__ __forceinline__ void gemm_body(
        int bid,
        const float* __restrict__ in, int in_stride,
        const float* __restrict__ W, const float* __restrict__ bias,
        float* __restrict__ out, int out_stride,
        float* __restrict__ out2, int out2_stride)
{
    constexpr int TX  = M / 4;        // threads across M (each owns 4 cols)
    constexpr int TY  = 256 / TX;
    constexpr int RPT = BR / TY;      // rows per thread
    constexpr int G   = M / 4;        // float4 groups per weight row

    __shared__ float4 in_sh[BR][KC / 4];     // 4 KB
    __shared__ float  wt_s[KC * M];          // <= 16 KB, W transposed+rotated

    const int tid  = threadIdx.x;
    const int tx   = tid % TX;
    const int ty   = tid / TX;
    const int row0 = bid * BR;

    float4 acc[RPT];
#pragma unroll
    for (int r = 0; r < RPT; r++) acc[r] = make_float4(0.f, 0.f, 0.f, 0.f);

    for (int k0 = 0; k0 < K; k0 += KC) {
        // ---- input tile (coalesced float4): 256 float4 by 256 threads ----
        {
            int r = tid >> 3;
            int v = tid & 7;
            in_sh[r][v] = *(const float4*)(in + (size_t)(row0 + r) * in_stride + k0 + v * 4);
        }
        // ---- weight tile, transposed with rotation (conflict-free STS) ----
        {
            int v = tid & 7;
#pragma unroll
            for (int m = tid >> 3; m < M; m += 32) {
                float4 w = *(const float4*)(W + (size_t)m * K + k0 + v * 4);
                int g  = m >> 2;
                int ml = m & 3;
                float wc[4] = {w.x, w.y, w.z, w.w};
#pragma unroll
                for (int c = 0; c < 4; c++) {
                    int k  = v * 4 + c;
                    int gp = (g + k + (k >> 2)) & (G - 1);
                    wt_s[k * M + gp * 4 + ml] = wc[c];
                }
            }
        }
        __syncthreads();

#pragma unroll
        for (int kv = 0; kv < KC / 4; kv++) {
            float4 w[4];
#pragma unroll
            for (int c = 0; c < 4; c++) {
                int k  = kv * 4 + c;
                int gp = (tx + k + (k >> 2)) & (G - 1);
                w[c] = *(const float4*)&wt_s[k * M + gp * 4];
            }
#pragma unroll
            for (int rr = 0; rr < RPT; rr++) {
                float4 a = in_sh[ty * RPT + rr][kv];
                acc[rr].x += a.x * w[0].x + a.y * w[1].x + a.z * w[2].x + a.w * w[3].x;
                acc[rr].y += a.x * w[0].y + a.y * w[1].y + a.z * w[2].y + a.w * w[3].y;
                acc[rr].z += a.x * w[0].z + a.y * w[1].z + a.z * w[2].z + a.w * w[3].z;
                acc[rr].w += a.x * w[0].w + a.y * w[1].w + a.z * w[2].w + a.w * w[3].w;
            }
        }
        __syncthreads();
    }

    float4 bb = make_float4(0.f, 0.f, 0.f, 0.f);
    if (bias) bb = *(const float4*)(bias + tx * 4);

#pragma unroll
    for (int rr = 0; rr < RPT; rr++) {
        int r = row0 + ty * RPT + rr;
        float4 o;
        o.x = acc[rr].x + bb.x;
        o.y = acc[rr].y + bb.y;
        o.z = acc[rr].z + bb.z;
        o.w = acc[rr].w + bb.w;
        if (RELU) {
            o.x = fmaxf(o.x, 0.f); o.y = fmaxf(o.y, 0.f);
            o.z = fmaxf(o.z, 0.f); o.w = fmaxf(o.w, 0.f);
        }
        *(float4*)(out + (size_t)r * out_stride + tx * 4) = o;
        if (out2)
            *(float4*)(out2 + (size_t)r * out2_stride + tx * 4) = o;
    }
}

// ---------------- fused GEMM + adjacency-scan kernel ------------------------
template <int K, int M, bool RELU, int KID>
__global__ void __launch_bounds__(256)
gemm_scan(const float* __restrict__ in, int in_stride,
          const float* __restrict__ W, const float* __restrict__ bias,
          float* __restrict__ out, int out_stride,
          float* __restrict__ out2, int out2_stride,
          const float* __restrict__ adj)
{
    if ((int)blockIdx.x >= GB) {         // side blocks: stream adj rows
        scan_rows(adj, KID);
        return;
    }
    gemm_body<K, M, RELU>(blockIdx.x, in, in_stride, W, bias,
                          out, out_stride, out2, out2_stride);
    if (threadIdx.x == 0) {
        if (atomicAdd(&g_fin[KID], 1) == GB - 1)
            atomicExch(&g_stop[KID], 1);  // hint: stop stealing, kernel done
    }
}

// plain GEMM (decoder path, no scan work left)
template <int K, int M, bool RELU>
__global__ void __launch_bounds__(256)
gemm_rt(const float* __restrict__ in, int in_stride,
        const float* __restrict__ W, const float* __restrict__ bias,
        float* __restrict__ out, int out_stride,
        float* __restrict__ out2, int out2_stride)
{
    gemm_body<K, M, RELU>(blockIdx.x, in, in_stride, W, bias,
                          out, out_stride, out2, out2_stride);
}

// ---------------- sparse aggregation + relu(agg + bg) ----------------------
__global__ void __launch_bounds__(128)
agg_kernel(const float* __restrict__ msg, const float* __restrict__ bg,
           float* __restrict__ g)
{
    const int row = blockIdx.x;
    const int c   = threadIdx.x;

    __shared__ int   s_idx[MAXD];
    __shared__ float s_dj [MAXD];

    const int   cnt = d_cnt[row];
    const float di  = d_dinv[row];

    if (c < cnt) {
        int j = d_nbr[(size_t)row * MAXD + c];
        s_idx[c] = j;
        s_dj[c]  = d_dinv[j];
    }
    __syncthreads();

    float acc0 = di * msg[(size_t)row * 128 + c];   // self-loop term
    float acc1 = 0.f;
    int k = 0;
    for (; k + 1 < cnt; k += 2) {
        acc0 += s_dj[k]     * msg[(size_t)s_idx[k]     * 128 + c];
        acc1 += s_dj[k + 1] * msg[(size_t)s_idx[k + 1] * 128 + c];
    }
    if (k < cnt) acc0 += s_dj[k] * msg[(size_t)s_idx[k] * 128 + c];

    float v = di * (acc0 + acc1) + bg[c];
    g[(size_t)row * 128 + c] = fmaxf(v, 0.f);
}

// ---------------- final small GEMM (M=8) + mask -----------------------------
__global__ void __launch_bounds__(256)
out_kernel(const float* __restrict__ q,   // [N,64]
           const float* __restrict__ wo,  // [8,64]
           const float* __restrict__ bo,  // [8]
           const float* __restrict__ mask,
           float* __restrict__ out)       // [N,8]
{
    __shared__ float q_sh[32][65];
    __shared__ float wo_sh[8][65];
    __shared__ float bo_sh[8];

    const int tid  = threadIdx.x;
    const int row0 = blockIdx.x * 32;

    for (int i = tid; i < 32 * 64; i += 256) {
        int r = i / 64, k = i % 64;
        q_sh[r][k] = q[(size_t)(row0 + r) * 64 + k];
    }
    for (int i = tid; i < 8 * 64; i += 256)
        wo_sh[i / 64][i % 64] = wo[i];
    if (tid < 8) bo_sh[tid] = bo[tid];
    __syncthreads();

    const int r = tid / 8, m = tid % 8;
    float acc = 0.f;
#pragma unroll
    for (int k = 0; k < 64; k++) acc += q_sh[r][k] * wo_sh[m][k];

    out[(size_t)(row0 + r) * 8 + m] = (acc + bo_sh[m]) * mask[row0 + r];
}

// ---------------- launch ----------------------------------------------------
extern "C" void kernel_launch(void* const* d_in, const int* in_sizes, int n_in,
                              void* d_out, int out_size)
{
    const float* x    = (const float*)d_in[0];
    const float* adj  = (const float*)d_in[1];
    const float* mask = (const float*)d_in[2];
    const float* w1   = (const float*)d_in[3];
    const float* b1   = (const float*)d_in[4];
    const float* w2   = (const float*)d_in[5];
    const float* b2   = (const float*)d_in[6];
    const float* wg   = (const float*)d_in[7];
    const float* bg   = (const float*)d_in[8];
    const float* wd   = (const float*)d_in[9];
    const float* bd   = (const float*)d_in[10];
    const float* wp1  = (const float*)d_in[11];
    const float* bp1  = (const float*)d_in[12];
    const float* wp2  = (const float*)d_in[13];
    const float* bp2  = (const float*)d_in[14];
    const float* wo   = (const float*)d_in[15];
    const float* bo   = (const float*)d_in[16];
    float* out = (float*)d_out;

    float *p_h1, *p_h, *p_msg, *p_g, *p_f, *p_p1, *p_p2;
    cudaGetSymbolAddress((void**)&p_h1,  d_h1);
    cudaGetSymbolAddress((void**)&p_h,   d_h);
    cudaGetSymbolAddress((void**)&p_msg, d_msg);
    cudaGetSymbolAddress((void**)&p_g,   d_g);
    cudaGetSymbolAddress((void**)&p_f,   d_f);
    cudaGetSymbolAddress((void**)&p_p1,  d_p1);
    cudaGetSymbolAddress((void**)&p_p2,  d_p2);

    init_kernel<<<1, 1>>>();

    // encoder GEMMs fused with adjacency scanning (disjoint resources:
    // fma pipe vs DRAM streaming)
    gemm_scan<32,  64,  true, 0><<<GB + SCANB, 256>>>(x,    32, w1, b1, p_h1, 64,  nullptr, 0, adj);
    gemm_scan<64,  128, true, 1><<<GB + SCANB, 256>>>(p_h1, 64, w2, b2, p_h,  128, p_f + 128, 256, adj);
    gemm_scan<128, 128, false,2><<<GB + SCANB, 256>>>(p_h, 128, wg, nullptr, p_msg, 128, nullptr, 0, adj);

    // drain remaining adjacency rows
    scan_finish_kernel<<<592, 256>>>(adj);

    // normalized aggregation + relu(+bg)
    agg_kernel<<<N_NODES, 128>>>(p_msg, bg, p_g);

    // decoder
    gemm_rt<128, 128, true><<<GB, 256>>>(p_g,  128, wd,  bd,  p_f,  256, nullptr, 0);
    gemm_rt<256, 128, true><<<GB, 256>>>(p_f,  256, wp1, bp1, p_p1, 128, nullptr, 0);
    gemm_rt<128, 64,  true><<<GB, 256>>>(p_p1, 128, wp2, bp2, p_p2, 64,  nullptr, 0);

    // output + mask
    out_kernel<<<N_NODES / 32, 256>>>(p_p2, wo, bo, mask, out);
}

// round 3
// speedup vs baseline: 1.3028x; 1.3028x over previous
#include <cuda_runtime.h>
#include <math.h>

#define N_NODES 8192
#define MAXD 128
constexpr int KC = 32;   // GEMM k-chunk

// ---------------- scratch (device globals) ----------------------------------
__device__ __align__(16) float d_msg[N_NODES * 128];
__device__ __align__(16) float d_f  [N_NODES * 256];   // [g*wd | h]
__device__ float d_dinv[N_NODES];
__device__ int   d_cnt [N_NODES];
__device__ int   d_nbr [N_NODES * MAXD];

// ---------------- adjacency scan: degree + capped CSR -----------------------
__global__ void __launch_bounds__(256)
degcsr_kernel(const float* __restrict__ adj)
{
    const int row = blockIdx.x;
    __shared__ int s_cnt;
    if (threadIdx.x == 0) s_cnt = 0;
    __syncthreads();

    const float4* a4 = (const float4*)(adj + (size_t)row * N_NODES);
    int* nbr = d_nbr + (size_t)row * MAXD;

    for (int i = threadIdx.x; i < N_NODES / 4; i += 256) {
        float4 v = __ldcs(&a4[i]);   // streaming: evict-first, don't pollute L2
        if (v.x != 0.f) { int p = atomicAdd(&s_cnt, 1); if (p < MAXD) nbr[p] = i * 4 + 0; }
        if (v.y != 0.f) { int p = atomicAdd(&s_cnt, 1); if (p < MAXD) nbr[p] = i * 4 + 1; }
        if (v.z != 0.f) { int p = atomicAdd(&s_cnt, 1); if (p < MAXD) nbr[p] = i * 4 + 2; }
        if (v.w != 0.f) { int p = atomicAdd(&s_cnt, 1); if (p < MAXD) nbr[p] = i * 4 + 3; }
    }
    __syncthreads();
    if (threadIdx.x == 0) {
        int cn = s_cnt;
        d_cnt[row]  = cn < MAXD ? cn : MAXD;
        d_dinv[row] = rsqrtf((float)cn + 1.0f);   // +1 self loop
    }
}

// ---------------- smem->smem/gmem register-tiled GEMM ------------------------
// out = act(in_s @ W^T + b). in_s: smem [32 rows, stride in_ss].
// Weight tile transposed into wt_s with per-k rotation (conflict-free STS/LDS).
template <int K, int M, bool RELU>
__device__ __forceinline__ void mlp_gemm(
        const float* in_s, int in_ss,
        const float* __restrict__ W, const float* __restrict__ bias,
        float* wt_s,
        float* out_s, int out_ss,
        float* out_g, int out_gs, int row0)
{
    constexpr int TX  = M / 4;
    constexpr int TY  = 256 / TX;
    constexpr int RPT = 32 / TY;
    constexpr int G   = M / 4;

    const int tid = threadIdx.x;
    const int tx  = tid % TX;
    const int ty  = tid / TX;

    float4 acc[RPT];
#pragma unroll
    for (int r = 0; r < RPT; r++) acc[r] = make_float4(0.f, 0.f, 0.f, 0.f);

    for (int k0 = 0; k0 < K; k0 += KC) {
        {   // weight tile, transposed + rotated
            int v = tid & 7;
#pragma unroll
            for (int m = tid >> 3; m < M; m += 32) {
                float4 w = *(const float4*)(W + (size_t)m * K + k0 + v * 4);
                int g = m >> 2, ml = m & 3;
                float wc[4] = {w.x, w.y, w.z, w.w};
#pragma unroll
                for (int c = 0; c < 4; c++) {
                    int k  = v * 4 + c;
                    int gp = (g + k + (k >> 2)) & (G - 1);
                    wt_s[k * M + gp * 4 + ml] = wc[c];
                }
            }
        }
        __syncthreads();

#pragma unroll
        for (int kv = 0; kv < KC / 4; kv++) {
            float4 w[4];
#pragma unroll
            for (int c = 0; c < 4; c++) {
                int k  = kv * 4 + c;
                int gp = (tx + k + (k >> 2)) & (G - 1);
                w[c] = *(const float4*)&wt_s[k * M + gp * 4];
            }
#pragma unroll
            for (int rr = 0; rr < RPT; rr++) {
                float4 a = *(const float4*)&in_s[(ty * RPT + rr) * in_ss + k0 + kv * 4];
                acc[rr].x += a.x * w[0].x + a.y * w[1].x + a.z * w[2].x + a.w * w[3].x;
                acc[rr].y += a.x * w[0].y + a.y * w[1].y + a.z * w[2].y + a.w * w[3].y;
                acc[rr].z += a.x * w[0].z + a.y * w[1].z + a.z * w[2].z + a.w * w[3].z;
                acc[rr].w += a.x * w[0].w + a.y * w[1].w + a.z * w[2].w + a.w * w[3].w;
            }
        }
        __syncthreads();
    }

    float4 bb = make_float4(0.f, 0.f, 0.f, 0.f);
    if (bias) bb = *(const float4*)(bias + tx * 4);

#pragma unroll
    for (int rr = 0; rr < RPT; rr++) {
        int r = ty * RPT + rr;
        float4 o;
        o.x = acc[rr].x + bb.x;  o.y = acc[rr].y + bb.y;
        o.z = acc[rr].z + bb.z;  o.w = acc[rr].w + bb.w;
        if (RELU) {
            o.x = fmaxf(o.x, 0.f); o.y = fmaxf(o.y, 0.f);
            o.z = fmaxf(o.z, 0.f); o.w = fmaxf(o.w, 0.f);
        }
        if (out_s) *(float4*)&out_s[r * out_ss + tx * 4] = o;
        if (out_g) *(float4*)(out_g + (size_t)(row0 + r) * out_gs + tx * 4) = o;
    }
}

// ---------------- fused encoder: x -> h1 -> h -> msg -------------------------
__global__ void __launch_bounds__(256)
encoder_kernel(const float* __restrict__ x,
               const float* __restrict__ w1, const float* __restrict__ b1,
               const float* __restrict__ w2, const float* __restrict__ b2,
               const float* __restrict__ wg,
               float* __restrict__ f, float* __restrict__ msg)
{
    __shared__ float s_a[32 * 128];   // x (first 1024 floats), later h
    __shared__ float s_b[32 * 64];    // h1
    __shared__ float wt [KC * 128];

    const int tid  = threadIdx.x;
    const int row0 = blockIdx.x * 32;

    {   // load x tile [32,32]
        int r = tid >> 3, v = tid & 7;
        *(float4*)&s_a[r * 32 + v * 4] =
            *(const float4*)(x + (size_t)(row0 + r) * 32 + v * 4);
    }
    __syncthreads();

    mlp_gemm<32, 64, true>(s_a, 32, w1, b1, wt, s_b, 64, nullptr, 0, 0);
    __syncthreads();
    // h -> smem AND f[:,128:256] (concat buffer)
    mlp_gemm<64, 128, true>(s_b, 64, w2, b2, wt, s_a, 128, f + 128, 256, row0);
    __syncthreads();
    // msg -> gmem
    mlp_gemm<128, 128, false>(s_a, 128, wg, nullptr, wt, nullptr, 0, msg, 128, row0);
}

// ---------------- fused decoder: agg -> wd -> wp1 -> wp2 -> wo*mask ----------
__global__ void __launch_bounds__(256)
decoder_kernel(const float* __restrict__ msg, const float* __restrict__ bg,
               const float* __restrict__ wd,  const float* __restrict__ bd,
               const float* __restrict__ wp1, const float* __restrict__ bp1,
               const float* __restrict__ wp2, const float* __restrict__ bp2,
               const float* __restrict__ wo,  const float* __restrict__ bo,
               const float* __restrict__ mask,
               const float* __restrict__ f_g,   // gmem f (h in cols 128:256)
               float* __restrict__ out)
{
    extern __shared__ float sm[];
    float* s_f  = sm;            // [32][256]
    float* s_t  = sm + 8192;     // [32][128]  g, then p1
    float* wt   = sm + 12288;    // [KC][128]
    float* s_wo = sm + 16384;    // [8][64]
    float* s_bo = sm + 16896;    // [8]
    float* s_p2 = s_f;           // reuse: [32][64] after s_f is dead

    const int tid  = threadIdx.x;
    const int row0 = blockIdx.x * 32;
    const int wid  = tid >> 5, lane = tid & 31;

    // load h half of f into smem (cols 128:256)
    for (int i = tid; i < 32 * 32; i += 256) {
        int r = i >> 5, v = i & 31;
        *(float4*)&s_f[r * 256 + 128 + v * 4] =
            *(const float4*)(f_g + (size_t)(row0 + r) * 256 + 128 + v * 4);
    }
    // wo/bo to smem
    for (int i = tid; i < 512; i += 256) s_wo[i] = wo[i];
    if (tid < 8) s_bo[tid] = bo[tid];

    // ---- aggregation: g = relu(dinv_i*(dinv_i*msg_i + sum dj*msg_j) + bg) ----
    const float4 bg4 = *(const float4*)(bg + lane * 4);
#pragma unroll
    for (int t = 0; t < 4; t++) {
        const int row = row0 + wid + t * 8;
        const int cnt = d_cnt[row];
        const float di = d_dinv[row];

        float4 m0 = *(const float4*)(msg + (size_t)row * 128 + lane * 4);
        float4 a0 = make_float4(di * m0.x, di * m0.y, di * m0.z, di * m0.w);
        float4 a1 = make_float4(0.f, 0.f, 0.f, 0.f);

        for (int b = 0; b < cnt; b += 32) {
            int   idx = 0; float dj = 0.f;
            if (b + lane < cnt) {
                idx = d_nbr[(size_t)row * MAXD + b + lane];
                dj  = d_dinv[idx];
            }
            const int mcnt = min(32, cnt - b);
            int u = 0;
            for (; u + 1 < mcnt; u += 2) {
                int   j0 = __shfl_sync(0xffffffffu, idx, u);
                float w0 = __shfl_sync(0xffffffffu, dj,  u);
                int   j1 = __shfl_sync(0xffffffffu, idx, u + 1);
                float w1 = __shfl_sync(0xffffffffu, dj,  u + 1);
                float4 v0 = *(const float4*)(msg + (size_t)j0 * 128 + lane * 4);
                float4 v1 = *(const float4*)(msg + (size_t)j1 * 128 + lane * 4);
                a0.x += w0 * v0.x; a0.y += w0 * v0.y; a0.z += w0 * v0.z; a0.w += w0 * v0.w;
                a1.x += w1 * v1.x; a1.y += w1 * v1.y; a1.z += w1 * v1.z; a1.w += w1 * v1.w;
            }
            if (u < mcnt) {
                int   j0 = __shfl_sync(0xffffffffu, idx, u);
                float w0 = __shfl_sync(0xffffffffu, dj,  u);
                float4 v0 = *(const float4*)(msg + (size_t)j0 * 128 + lane * 4);
                a0.x += w0 * v0.x; a0.y += w0 * v0.y; a0.z += w0 * v0.z; a0.w += w0 * v0.w;
            }
        }
        float4 g;
        g.x = fmaxf(di * (a0.x + a1.x) + bg4.x, 0.f);
        g.y = fmaxf(di * (a0.y + a1.y) + bg4.y, 0.f);
        g.z = fmaxf(di * (a0.z + a1.z) + bg4.z, 0.f);
        g.w = fmaxf(di * (a0.w + a1.w) + bg4.w, 0.f);
        *(float4*)&s_t[(row - row0) * 128 + lane * 4] = g;
    }
    __syncthreads();

    // d = relu(g @ wd^T + bd) -> s_f cols 0:128
    mlp_gemm<128, 128, true>(s_t, 128, wd, bd, wt, s_f, 256, nullptr, 0, 0);
    __syncthreads();
    // p1 = relu(f @ wp1^T + bp1)
    mlp_gemm<256, 128, true>(s_f, 256, wp1, bp1, wt, s_t, 128, nullptr, 0, 0);
    __syncthreads();
    // p2 = relu(p1 @ wp2^T + bp2)  (into s_f region, now dead)
    mlp_gemm<128, 64, true>(s_t, 128, wp2, bp2, wt, s_p2, 64, nullptr, 0, 0);
    __syncthreads();

    // out = (p2 @ wo^T + bo) * mask
    {
        const int r = tid >> 3, m = tid & 7;
        float acc = 0.f;
#pragma unroll
        for (int k = 0; k < 64; k++) acc += s_p2[r * 64 + k] * s_wo[m * 64 + k];
        out[(size_t)(row0 + r) * 8 + m] = (acc + s_bo[m]) * mask[row0 + r];
    }
}

// ---------------- launch -----------------------------------------------------
extern "C" void kernel_launch(void* const* d_in, const int* in_sizes, int n_in,
                              void* d_out, int out_size)
{
    const float* x    = (const float*)d_in[0];
    const float* adj  = (const float*)d_in[1];
    const float* mask = (const float*)d_in[2];
    const float* w1   = (const float*)d_in[3];
    const float* b1   = (const float*)d_in[4];
    const float* w2   = (const float*)d_in[5];
    const float* b2   = (const float*)d_in[6];
    const float* wg   = (const float*)d_in[7];
    const float* bg   = (const float*)d_in[8];
    const float* wd   = (const float*)d_in[9];
    const float* bd   = (const float*)d_in[10];
    const float* wp1  = (const float*)d_in[11];
    const float* bp1  = (const float*)d_in[12];
    const float* wp2  = (const float*)d_in[13];
    const float* bp2  = (const float*)d_in[14];
    const float* wo   = (const float*)d_in[15];
    const float* bo   = (const float*)d_in[16];
    float* out = (float*)d_out;

    float *p_msg, *p_f;
    cudaGetSymbolAddress((void**)&p_msg, d_msg);
    cudaGetSymbolAddress((void**)&p_f,   d_f);

    static int smem_set = 0;
    const int DEC_SMEM = (16384 + 512 + 8) * 4;
    if (!smem_set) {
        cudaFuncSetAttribute(decoder_kernel,
                             cudaFuncAttributeMaxDynamicSharedMemorySize, DEC_SMEM);
        smem_set = 1;
    }

    degcsr_kernel<<<N_NODES, 256>>>(adj);
    encoder_kernel<<<N_NODES / 32, 256>>>(x, w1, b1, w2, b2, wg, p_f, p_msg);
    decoder_kernel<<<N_NODES / 32, 256, DEC_SMEM>>>(
        p_msg, bg, wd, bd, wp1, bp1, wp2, bp2, wo, bo, mask, p_f, out);
}

// round 4
// speedup vs baseline: 1.3402x; 1.0287x over previous
#include <cuda_runtime.h>
#include <math.h>

#define N_NODES 8192
#define MAXD 128
constexpr int KC = 32;   // GEMM k-chunk

// ---------------- scratch (device globals) ----------------------------------
__device__ __align__(16) float d_msg[N_NODES * 128];
__device__ __align__(16) float d_f  [N_NODES * 256];   // [g*wd | h]
__device__ float d_dinv[N_NODES];
__device__ int   d_cnt [N_NODES];
__device__ int   d_nbr [N_NODES * MAXD];

// ---------------- per-row adjacency scan (MLP=8 batched loads) --------------
__device__ __forceinline__ void scan_row(const float* __restrict__ adj, int row)
{
    __shared__ int s_cnt;
    const int tid = threadIdx.x;
    if (tid == 0) s_cnt = 0;
    __syncthreads();

    const float4* a4 = (const float4*)(adj + (size_t)row * N_NODES);
    int* nbr = d_nbr + (size_t)row * MAXD;

    float4 v[8];
#pragma unroll
    for (int u = 0; u < 8; u++)
        v[u] = __ldcs(&a4[tid + u * 256]);     // 8 independent loads in flight

#pragma unroll
    for (int u = 0; u < 8; u++) {
        const int base = (tid + u * 256) * 4;
        if (v[u].x != 0.f) { int p = atomicAdd(&s_cnt, 1); if (p < MAXD) nbr[p] = base + 0; }
        if (v[u].y != 0.f) { int p = atomicAdd(&s_cnt, 1); if (p < MAXD) nbr[p] = base + 1; }
        if (v[u].z != 0.f) { int p = atomicAdd(&s_cnt, 1); if (p < MAXD) nbr[p] = base + 2; }
        if (v[u].w != 0.f) { int p = atomicAdd(&s_cnt, 1); if (p < MAXD) nbr[p] = base + 3; }
    }
    __syncthreads();
    if (tid == 0) {
        int cn = s_cnt;
        d_cnt[row]  = cn < MAXD ? cn : MAXD;
        d_dinv[row] = rsqrtf((float)cn + 1.0f);   // +1 self loop
    }
}

// ---------------- register-tiled GEMM, double-buffered weight tiles ---------
// out = act(in_s @ W^T + b); in_s in smem. wt_s must hold 2*KC*M floats.
template <int K, int M, bool RELU>
__device__ __forceinline__ void mlp_gemm(
        const float* in_s, int in_ss,
        const float* __restrict__ W, const float* __restrict__ bias,
        float* wt_s,
        float* out_s, int out_ss,
        float* out_g, int out_gs, int row0)
{
    constexpr int TX  = M / 4;
    constexpr int TY  = 256 / TX;
    constexpr int RPT = 32 / TY;
    constexpr int G   = M / 4;
    constexpr int CH  = K / KC;
    constexpr int FR  = M / 32;      // weight fragments per thread

    const int tid = threadIdx.x;
    const int tx  = tid % TX;
    const int ty  = tid / TX;
    const int v   = tid & 7;
    const int m0  = tid >> 3;

    float4 acc[RPT];
#pragma unroll
    for (int r = 0; r < RPT; r++) acc[r] = make_float4(0.f, 0.f, 0.f, 0.f);

    float4 wreg[FR];
#pragma unroll
    for (int i = 0; i < FR; i++)
        wreg[i] = *(const float4*)(W + (size_t)(m0 + 32 * i) * K + v * 4);

    // store chunk 0 (transposed + rotated: conflict-free STS/LDS)
#pragma unroll
    for (int i = 0; i < FR; i++) {
        int m = m0 + 32 * i, g = m >> 2, ml = m & 3;
        float wc[4] = {wreg[i].x, wreg[i].y, wreg[i].z, wreg[i].w};
#pragma unroll
        for (int c = 0; c < 4; c++) {
            int k  = v * 4 + c;
            int gp = (g + k + (k >> 2)) & (G - 1);
            wt_s[k * M + gp * 4 + ml] = wc[c];
        }
    }
    __syncthreads();

#pragma unroll
    for (int ch = 0; ch < CH; ch++) {
        if (ch + 1 < CH) {   // prefetch next weight chunk (hidden under compute)
#pragma unroll
            for (int i = 0; i < FR; i++)
                wreg[i] = *(const float4*)(W + (size_t)(m0 + 32 * i) * K
                                           + (ch + 1) * KC + v * 4);
        }
        const float* buf = wt_s + (ch & 1) * (KC * M);
        const int k0 = ch * KC;

#pragma unroll
        for (int kv = 0; kv < KC / 4; kv++) {
            float4 w[4];
#pragma unroll
            for (int c = 0; c < 4; c++) {
                int k  = kv * 4 + c;
                int gp = (tx + k + (k >> 2)) & (G - 1);
                w[c] = *(const float4*)&buf[k * M + gp * 4];
            }
#pragma unroll
            for (int rr = 0; rr < RPT; rr++) {
                float4 a = *(const float4*)&in_s[(ty * RPT + rr) * in_ss + k0 + kv * 4];
                acc[rr].x += a.x * w[0].x + a.y * w[1].x + a.z * w[2].x + a.w * w[3].x;
                acc[rr].y += a.x * w[0].y + a.y * w[1].y + a.z * w[2].y + a.w * w[3].y;
                acc[rr].z += a.x * w[0].z + a.y * w[1].z + a.z * w[2].z + a.w * w[3].z;
                acc[rr].w += a.x * w[0].w + a.y * w[1].w + a.z * w[2].w + a.w * w[3].w;
            }
        }

        if (ch + 1 < CH) {   // store prefetched chunk into the other buffer
            float* nbuf = wt_s + ((ch + 1) & 1) * (KC * M);
#pragma unroll
            for (int i = 0; i < FR; i++) {
                int m = m0 + 32 * i, g = m >> 2, ml = m & 3;
                float wc[4] = {wreg[i].x, wreg[i].y, wreg[i].z, wreg[i].w};
#pragma unroll
                for (int c = 0; c < 4; c++) {
                    int k  = v * 4 + c;
                    int gp = (g + k + (k >> 2)) & (G - 1);
                    nbuf[k * M + gp * 4 + ml] = wc[c];
                }
            }
        }
        __syncthreads();
    }

    float4 bb = make_float4(0.f, 0.f, 0.f, 0.f);
    if (bias) bb = *(const float4*)(bias + tx * 4);

#pragma unroll
    for (int rr = 0; rr < RPT; rr++) {
        int r = ty * RPT + rr;
        float4 o;
        o.x = acc[rr].x + bb.x;  o.y = acc[rr].y + bb.y;
        o.z = acc[rr].z + bb.z;  o.w = acc[rr].w + bb.w;
        if (RELU) {
            o.x = fmaxf(o.x, 0.f); o.y = fmaxf(o.y, 0.f);
            o.z = fmaxf(o.z, 0.f); o.w = fmaxf(o.w, 0.f);
        }
        if (out_s) *(float4*)&out_s[r * out_ss + tx * 4] = o;
        if (out_g) *(float4*)(out_g + (size_t)(row0 + r) * out_gs + tx * 4) = o;
    }
}

// ---------------- fused: encoder blocks (0..255) + scan blocks (256..) ------
// Encoder (x -> h1 -> h -> msg) uses no scan output; scan rows statically
// assigned -> deterministic. Encoder blocks first so they join wave 1.
__global__ void __launch_bounds__(256)
enc_scan_kernel(const float* __restrict__ x,
                const float* __restrict__ w1, const float* __restrict__ b1,
                const float* __restrict__ w2, const float* __restrict__ b2,
                const float* __restrict__ wg,
                float* __restrict__ f, float* __restrict__ msg,
                const float* __restrict__ adj)
{
    if ((int)blockIdx.x >= N_NODES / 32) {
        scan_row(adj, (int)blockIdx.x - N_NODES / 32);
        return;
    }

    extern __shared__ float esm[];
    float* s_a = esm;            // 4096: x tile, later h
    float* s_b = esm + 4096;     // 2048: h1
    float* wt  = esm + 6144;     // 8192: double-buffered weight tiles

    const int tid  = threadIdx.x;
    const int row0 = blockIdx.x * 32;

    {   // load x tile [32,32]
        int r = tid >> 3, vv = tid & 7;
        *(float4*)&s_a[r * 32 + vv * 4] =
            *(const float4*)(x + (size_t)(row0 + r) * 32 + vv * 4);
    }
    __syncthreads();

    mlp_gemm<32, 64, true>(s_a, 32, w1, b1, wt, s_b, 64, nullptr, 0, 0);
    __syncthreads();
    mlp_gemm<64, 128, true>(s_b, 64, w2, b2, wt, s_a, 128, f + 128, 256, row0);
    __syncthreads();
    mlp_gemm<128, 128, false>(s_a, 128, wg, nullptr, wt, nullptr, 0, msg, 128, row0);
}

// ---------------- fused decoder: agg -> wd -> wp1 -> wp2 -> wo*mask ---------
__global__ void __launch_bounds__(256)
decoder_kernel(const float* __restrict__ msg, const float* __restrict__ bg,
               const float* __restrict__ wd,  const float* __restrict__ bd,
               const float* __restrict__ wp1, const float* __restrict__ bp1,
               const float* __restrict__ wp2, const float* __restrict__ bp2,
               const float* __restrict__ wo,  const float* __restrict__ bo,
               const float* __restrict__ mask,
               const float* __restrict__ f_g,
               float* __restrict__ out)
{
    extern __shared__ float sm[];
    float* s_f  = sm;            // [32][256]
    float* s_t  = sm + 8192;     // [32][128]: g, then p1
    float* wt   = sm + 12288;    // 8192: double-buffered weight tiles
    float* s_wo = sm + 20480;    // [8][64]
    float* s_bo = sm + 20992;    // [8]
    float* s_p2 = s_f;           // reuse after s_f dead

    const int tid  = threadIdx.x;
    const int row0 = blockIdx.x * 32;
    const int wid  = tid >> 5, lane = tid & 31;

    for (int i = tid; i < 32 * 32; i += 256) {   // h half of f
        int r = i >> 5, vv = i & 31;
        *(float4*)&s_f[r * 256 + 128 + vv * 4] =
            *(const float4*)(f_g + (size_t)(row0 + r) * 256 + 128 + vv * 4);
    }
    for (int i = tid; i < 512; i += 256) s_wo[i] = wo[i];
    if (tid < 8) s_bo[tid] = bo[tid];

    // ---- aggregation: g = relu(dinv_i*(dinv_i*msg_i + sum dj*msg_j) + bg) ----
    const float4 bg4 = *(const float4*)(bg + lane * 4);
#pragma unroll
    for (int t = 0; t < 4; t++) {
        const int row = row0 + wid + t * 8;
        const int cnt = d_cnt[row];
        const float di = d_dinv[row];

        float4 m0 = *(const float4*)(msg + (size_t)row * 128 + lane * 4);
        float4 a0 = make_float4(di * m0.x, di * m0.y, di * m0.z, di * m0.w);
        float4 a1 = make_float4(0.f, 0.f, 0.f, 0.f);
        float4 a2 = make_float4(0.f, 0.f, 0.f, 0.f);
        float4 a3 = make_float4(0.f, 0.f, 0.f, 0.f);

        for (int b = 0; b < cnt; b += 32) {
            int idx = 0; float dj = 0.f;
            if (b + lane < cnt) {
                idx = d_nbr[(size_t)row * MAXD + b + lane];
                dj  = d_dinv[idx];
            }
            const int mcnt = min(32, cnt - b);
            int u = 0;
            for (; u + 3 < mcnt; u += 4) {       // 4 gathers in flight
                int   j0 = __shfl_sync(0xffffffffu, idx, u);
                int   j1 = __shfl_sync(0xffffffffu, idx, u + 1);
                int   j2 = __shfl_sync(0xffffffffu, idx, u + 2);
                int   j3 = __shfl_sync(0xffffffffu, idx, u + 3);
                float w0 = __shfl_sync(0xffffffffu, dj, u);
                float w1 = __shfl_sync(0xffffffffu, dj, u + 1);
                float w2 = __shfl_sync(0xffffffffu, dj, u + 2);
                float w3 = __shfl_sync(0xffffffffu, dj, u + 3);
                float4 v0 = *(const float4*)(msg + (size_t)j0 * 128 + lane * 4);
                float4 v1 = *(const float4*)(msg + (size_t)j1 * 128 + lane * 4);
                float4 v2 = *(const float4*)(msg + (size_t)j2 * 128 + lane * 4);
                float4 v3 = *(const float4*)(msg + (size_t)j3 * 128 + lane * 4);
                a0.x += w0 * v0.x; a0.y += w0 * v0.y; a0.z += w0 * v0.z; a0.w += w0 * v0.w;
                a1.x += w1 * v1.x; a1.y += w1 * v1.y; a1.z += w1 * v1.z; a1.w += w1 * v1.w;
                a2.x += w2 * v2.x; a2.y += w2 * v2.y; a2.z += w2 * v2.z; a2.w += w2 * v2.w;
                a3.x += w3 * v3.x; a3.y += w3 * v3.y; a3.z += w3 * v3.z; a3.w += w3 * v3.w;
            }
            for (; u < mcnt; u++) {
                int   j0 = __shfl_sync(0xffffffffu, idx, u);
                float w0 = __shfl_sync(0xffffffffu, dj, u);
                float4 v0 = *(const float4*)(msg + (size_t)j0 * 128 + lane * 4);
                a0.x += w0 * v0.x; a0.y += w0 * v0.y; a0.z += w0 * v0.z; a0.w += w0 * v0.w;
            }
        }
        float4 g;
        g.x = fmaxf(di * ((a0.x + a1.x) + (a2.x + a3.x)) + bg4.x, 0.f);
        g.y = fmaxf(di * ((a0.y + a1.y) + (a2.y + a3.y)) + bg4.y, 0.f);
        g.z = fmaxf(di * ((a0.z + a1.z) + (a2.z + a3.z)) + bg4.z, 0.f);
        g.w = fmaxf(di * ((a0.w + a1.w) + (a2.w + a3.w)) + bg4.w, 0.f);
        *(float4*)&s_t[(row - row0) * 128 + lane * 4] = g;
    }
    __syncthreads();

    mlp_gemm<128, 128, true>(s_t, 128, wd, bd, wt, s_f, 256, nullptr, 0, 0);
    __syncthreads();
    mlp_gemm<256, 128, true>(s_f, 256, wp1, bp1, wt, s_t, 128, nullptr, 0, 0);
    __syncthreads();
    mlp_gemm<128, 64, true>(s_t, 128, wp2, bp2, wt, s_p2, 64, nullptr, 0, 0);
    __syncthreads();

    {   // out = (p2 @ wo^T + bo) * mask
        const int r = tid >> 3, m = tid & 7;
        float acc = 0.f;
#pragma unroll
        for (int k = 0; k < 64; k++) acc += s_p2[r * 64 + k] * s_wo[m * 64 + k];
        out[(size_t)(row0 + r) * 8 + m] = (acc + s_bo[m]) * mask[row0 + r];
    }
}

// ---------------- launch -----------------------------------------------------
extern "C" void kernel_launch(void* const* d_in, const int* in_sizes, int n_in,
                              void* d_out, int out_size)
{
    const float* x    = (const float*)d_in[0];
    const float* adj  = (const float*)d_in[1];
    const float* mask = (const float*)d_in[2];
    const float* w1   = (const float*)d_in[3];
    const float* b1   = (const float*)d_in[4];
    const float* w2   = (const float*)d_in[5];
    const float* b2   = (const float*)d_in[6];
    const float* wg   = (const float*)d_in[7];
    const float* bg   = (const float*)d_in[8];
    const float* wd   = (const float*)d_in[9];
    const float* bd   = (const float*)d_in[10];
    const float* wp1  = (const float*)d_in[11];
    const float* bp1  = (const float*)d_in[12];
    const float* wp2  = (const float*)d_in[13];
    const float* bp2  = (const float*)d_in[14];
    const float* wo   = (const float*)d_in[15];
    const float* bo   = (const float*)d_in[16];
    float* out = (float*)d_out;

    float *p_msg, *p_f;
    cudaGetSymbolAddress((void**)&p_msg, d_msg);
    cudaGetSymbolAddress((void**)&p_f,   d_f);

    const int ENC_SMEM = (4096 + 2048 + 8192) * 4;           // 57344 B
    const int DEC_SMEM = (8192 + 4096 + 8192 + 512 + 8) * 4; // 84000 B
    static int smem_set = 0;
    if (!smem_set) {
        cudaFuncSetAttribute(enc_scan_kernel,
                             cudaFuncAttributeMaxDynamicSharedMemorySize, ENC_SMEM);
        cudaFuncSetAttribute(decoder_kernel,
                             cudaFuncAttributeMaxDynamicSharedMemorySize, DEC_SMEM);
        smem_set = 1;
    }

    enc_scan_kernel<<<N_NODES / 32 + N_NODES, 256, ENC_SMEM>>>(
        x, w1, b1, w2, b2, wg, p_f, p_msg, adj);
    decoder_kernel<<<N_NODES / 32, 256, DEC_SMEM>>>(
        p_msg, bg, wd, bd, wp1, bp1, wp2, bp2, wo, bo, mask, p_f, out);
}